// round 12
// baseline (speedup 1.0000x reference)
#include <cuda_runtime.h>
#include <math.h>
#include <stdint.h>

#define NN 768
#define HH 12
#define CS 384
#define PROJ_N 1152
#define FEAT_N 2112   // [o 192 | ptx 96 | pty 96 | ptz 96 | ptnorm 96 | opair 1536]

typedef unsigned long long ull;

#define S1 0.14433756729740643f      // sqrt(1/48)
#define SQ13 0.5773502691896258f     // sqrt(1/3)
#define HWF 0.13608276348795434f     // sqrt(1/54)

__device__ __forceinline__ void ffma2(ull& d, ull a, ull b) {
    asm("fma.rn.f32x2 %0, %1, %2, %0;" : "+l"(d) : "l"(a), "l"(b));
}
__device__ __forceinline__ ull pack2(float x, float y) {
    ull r; asm("mov.b64 %0, {%1, %2};" : "=l"(r) : "f"(x), "f"(y)); return r;
}
__device__ __forceinline__ float2 unpack2(ull v) {
    float2 r; asm("mov.b64 {%0, %1}, %2;" : "=f"(r.x), "=f"(r.y) : "l"(v)); return r;
}
__device__ __forceinline__ uint32_t to_tf32(float f) {
    uint32_t r; asm("cvt.rna.tf32.f32 %0, %1;" : "=r"(r) : "f"(f)); return r;
}
__device__ __forceinline__ void mma_tf32(float c[4],
    uint32_t a0, uint32_t a1, uint32_t a2, uint32_t a3,
    uint32_t b0, uint32_t b1)
{
    asm("mma.sync.aligned.m16n8k8.row.col.f32.tf32.tf32.f32 "
        "{%0,%1,%2,%3}, {%4,%5,%6,%7}, {%8,%9}, {%0,%1,%2,%3};"
        : "+f"(c[0]), "+f"(c[1]), "+f"(c[2]), "+f"(c[3])
        : "r"(a0), "r"(a1), "r"(a2), "r"(a3), "r"(b0), "r"(b1));
}

// ---------------- scratch ----------------
__device__ float g_proj[NN * PROJ_N];
__device__ float g_v[NN * 192];
__device__ float g_vpts[NN * 288];
__device__ float g_qb[HH * NN * 32];
__device__ float g_kb[HH * NN * 32];
__device__ float g_qkp[(size_t)NN * HH * NN]; // [i][h][j]
__device__ float g_a[(size_t)NN * HH * NN];   // [i][h][j]
__device__ float g_aT[(size_t)NN * NN * HH];  // [i][j][h]
__device__ float g_optg[NN * 288];
__device__ float g_feats[NN * FEAT_N];

// ---------------- GEMM: out = A @ W + bias, segmented over N ----------------
__global__ __launch_bounds__(256) void gemm_kernel(
    const float* __restrict__ A, int K,
    const float* __restrict__ w0, const float* __restrict__ w1,
    const float* __restrict__ w2, const float* __restrict__ w3,
    const float* __restrict__ b0, const float* __restrict__ b1,
    const float* __restrict__ b2, const float* __restrict__ b3,
    int e0, int e1, int e2, int e3,
    float* __restrict__ out, int ldo)
{
    __shared__ float As[16][34];
    __shared__ float Bs[16][64];

    const int m0 = blockIdx.y * 32;
    const int n0 = blockIdx.x * 64;
    const int t = threadIdx.x;

    const int bkr = t >> 4;
    const int n   = n0 + (t & 15) * 4;
    const float* W; const float* bias; int base, segN;
    if (n < e0)      { W = w0; bias = b0; base = 0;  segN = e0; }
    else if (n < e1) { W = w1; bias = b1; base = e0; segN = e1 - e0; }
    else if (n < e2) { W = w2; bias = b2; base = e1; segN = e2 - e1; }
    else             { W = w3; bias = b3; base = e2; segN = e3 - e2; }

    const int ar  = t >> 2;
    const int ac4 = (t & 3) * 4;
    const int ty  = t >> 4;
    const int tx  = t & 15;

    float acc[2][4] = {};

    for (int k0 = 0; k0 < K; k0 += 16) {
        if (t < 128) {
            float4 av = *(const float4*)&A[(size_t)(m0 + ar) * K + k0 + ac4];
            As[ac4 + 0][ar] = av.x; As[ac4 + 1][ar] = av.y;
            As[ac4 + 2][ar] = av.z; As[ac4 + 3][ar] = av.w;
        }
        float4 bv = *(const float4*)&W[(size_t)(k0 + bkr) * segN + (n - base)];
        *(float4*)&Bs[bkr][(t & 15) * 4] = bv;
        __syncthreads();
        #pragma unroll
        for (int kk = 0; kk < 16; kk++) {
            float2 a2 = *(const float2*)&As[kk][ty * 2];
            float4 b4 = *(const float4*)&Bs[kk][tx * 4];
            acc[0][0] += a2.x * b4.x; acc[0][1] += a2.x * b4.y;
            acc[0][2] += a2.x * b4.z; acc[0][3] += a2.x * b4.w;
            acc[1][0] += a2.y * b4.x; acc[1][1] += a2.y * b4.y;
            acc[1][2] += a2.y * b4.z; acc[1][3] += a2.y * b4.w;
        }
        __syncthreads();
    }
    float4 bb = *(const float4*)&bias[n - base];
    #pragma unroll
    for (int r = 0; r < 2; r++) {
        float4 o;
        o.x = acc[r][0] + bb.x; o.y = acc[r][1] + bb.y;
        o.z = acc[r][2] + bb.z; o.w = acc[r][3] + bb.w;
        *(float4*)&out[(size_t)(m0 + ty * 2 + r) * ldo + n] = o;
    }
}

// ---------------- prep ----------------
__global__ __launch_bounds__(384) void prep_kernel(
    const float* __restrict__ rot, const float* __restrict__ trans,
    const float* __restrict__ head_w)
{
    __shared__ float s_qp3[144];
    __shared__ float s_kp3[144];

    const int n = blockIdx.x;
    const int t = threadIdx.x;
    const float* pr = &g_proj[(size_t)n * PROJ_N];

    if (t < 192) {
        int h = t >> 4, c = t & 15;
        g_kb[((size_t)h * NN + n) * 32 + c] = pr[192 + h * 32 + c];
        g_v[n * 192 + t] = pr[192 + h * 32 + 16 + c];
    }
    float r[9], tr[3];
    #pragma unroll
    for (int e = 0; e < 9; e++) r[e] = rot[n * 9 + e];
    tr[0] = trans[n * 3 + 0]; tr[1] = trans[n * 3 + 1]; tr[2] = trans[n * 3 + 2];

    if (t < 48) {
        float p0 = pr[576 + 0 * 48 + t];
        float p1 = pr[576 + 1 * 48 + t];
        float p2 = pr[576 + 2 * 48 + t];
        #pragma unroll
        for (int ii = 0; ii < 3; ii++)
            s_qp3[t * 3 + ii] = r[ii * 3 + 0] * p0 + r[ii * 3 + 1] * p1 + r[ii * 3 + 2] * p2 + tr[ii];
    }
    if (t >= 64 && t < 208) {
        int u = t - 64;
        float p0 = pr[720 + 0 * 144 + u];
        float p1 = pr[720 + 1 * 144 + u];
        float p2 = pr[720 + 2 * 144 + u];
        int h = u / 12, p = u % 12;
        #pragma unroll
        for (int ii = 0; ii < 3; ii++) {
            float o = r[ii * 3 + 0] * p0 + r[ii * 3 + 1] * p1 + r[ii * 3 + 2] * p2 + tr[ii];
            if (p < 4) s_kp3[(h * 4 + p) * 3 + ii] = o;
            else       g_vpts[n * 288 + (h * 8 + (p - 4)) * 3 + ii] = o;
        }
    }
    __syncthreads();

    {
        int h = t >> 5, e = t & 31;
        float x = head_w[h];
        float hw = ((x > 20.f) ? x : log1pf(__expf(x))) * HWF;

        float qv;
        if (e < 16)       qv = pr[h * 16 + e] * S1;
        else if (e < 28)  qv = s_qp3[h * 12 + (e - 16)] * hw;
        else if (e == 28) qv = -0.5f * hw;
        else if (e == 29) {
            float nq = 0.f;
            #pragma unroll
            for (int d = 0; d < 12; d++) { float v = s_qp3[h * 12 + d]; nq += v * v; }
            qv = -0.5f * hw * nq;
        } else qv = 0.f;
        g_qb[((size_t)h * NN + n) * 32 + e] = qv;

        if (e >= 16) {
            float kv2;
            if (e < 28)       kv2 = s_kp3[h * 12 + (e - 16)];
            else if (e == 28) {
                float nk = 0.f;
                #pragma unroll
                for (int d = 0; d < 12; d++) { float v = s_kp3[h * 12 + d]; nk += v * v; }
                kv2 = nk;
            }
            else if (e == 29) kv2 = 1.f;
            else              kv2 = 0.f;
            g_kb[((size_t)h * NN + n) * 32 + e] = kv2;
        }
    }
}

// ---------------- qkpts ----------------
__global__ __launch_bounds__(256) void qkpts_kernel(const float* __restrict__ mask)
{
    __shared__ float As[32][68];
    __shared__ float Bs[32][68];
    __shared__ float s_mi[64], s_mj[64];

    const int i0 = blockIdx.x * 64;
    const int j0 = blockIdx.y * 64;
    const int h  = blockIdx.z;
    const int t = threadIdx.x;

    #pragma unroll
    for (int r2 = 0; r2 < 2; r2++) {
        int li = t + r2 * 256;
        int row = li >> 3, c4 = (li & 7) * 4;
        float4 a = *(const float4*)&g_qb[((size_t)h * NN + i0 + row) * 32 + c4];
        As[c4 + 0][row] = a.x; As[c4 + 1][row] = a.y;
        As[c4 + 2][row] = a.z; As[c4 + 3][row] = a.w;
        float4 b = *(const float4*)&g_kb[((size_t)h * NN + j0 + row) * 32 + c4];
        Bs[c4 + 0][row] = b.x; Bs[c4 + 1][row] = b.y;
        Bs[c4 + 2][row] = b.z; Bs[c4 + 3][row] = b.w;
    }
    if (t < 64)              s_mi[t] = mask[i0 + t];
    else if (t < 128)        s_mj[t - 64] = mask[j0 + t - 64];
    __syncthreads();

    const int ty = t >> 4, tx = t & 15;
    float acc[4][4] = {};
    #pragma unroll
    for (int k = 0; k < 32; k++) {
        float4 a4 = *(const float4*)&As[k][ty * 4];
        float4 b4 = *(const float4*)&Bs[k][tx * 4];
        acc[0][0] += a4.x * b4.x; acc[0][1] += a4.x * b4.y; acc[0][2] += a4.x * b4.z; acc[0][3] += a4.x * b4.w;
        acc[1][0] += a4.y * b4.x; acc[1][1] += a4.y * b4.y; acc[1][2] += a4.y * b4.z; acc[1][3] += a4.y * b4.w;
        acc[2][0] += a4.z * b4.x; acc[2][1] += a4.z * b4.y; acc[2][2] += a4.z * b4.z; acc[2][3] += a4.z * b4.w;
        acc[3][0] += a4.w * b4.x; acc[3][1] += a4.w * b4.y; acc[3][2] += a4.w * b4.z; acc[3][3] += a4.w * b4.w;
    }
    #pragma unroll
    for (int rr = 0; rr < 4; rr++) {
        float mi = s_mi[ty * 4 + rr];
        float4 o;
        o.x = acc[rr][0] + 100000.f * (mi * s_mj[tx * 4 + 0] - 1.f);
        o.y = acc[rr][1] + 100000.f * (mi * s_mj[tx * 4 + 1] - 1.f);
        o.z = acc[rr][2] + 100000.f * (mi * s_mj[tx * 4 + 2] - 1.f);
        o.w = acc[rr][3] + 100000.f * (mi * s_mj[tx * 4 + 3] - 1.f);
        *(float4*)&g_qkp[(size_t)(i0 + ty * 4 + rr) * 9216 + h * 768 + j0 + tx * 4] = o;
    }
}

// ---------------- attnsm: fused z-bias MMA + qkp add + softmax; write a / aT ----------------
// Block = one i, 256 thr (8 warps). 12 chunks of 64 z-rows staged as tf32 in smem;
// warp job per chunk: m-tile (16 rows) x n-half (8 heads). Logits written straight to s_l.
#define LP 772
#define AS_ZU 8448                      // 64*132 uint
#define AS_SMEM_BYTES ((AS_ZU + 12 * LP + 768) * 4)
__global__ __launch_bounds__(256, 2) void attnsm_kernel(
    const float* __restrict__ z, const float* __restrict__ ss,
    const float* __restrict__ w_b, const float* __restrict__ b_b)
{
    extern __shared__ uint32_t smu[];
    uint32_t* s_z = smu;                          // [64][132] tf32 bits
    float* s_l = (float*)(smu + AS_ZU);           // [12][LP]
    float* s_w = s_l + 12 * LP;                   // [768]

    const int i = blockIdx.x;
    const int t = threadIdx.x;
    const int w = t >> 5;
    const int lane = t & 31;
    const int tg = lane & 3;
    const int gp = lane >> 2;
    const int mt = w & 3;        // m-tile within 64-row chunk
    const int nh = w >> 2;       // n-half: heads 0-7 / 8-15(pad)

    // B fragments for this warp's n-half (cols nh*8 + 0..7; heads >=12 zero)
    uint32_t Bf[16][2];
    {
        const int col = nh * 8 + gp;
        #pragma unroll
        for (int kk = 0; kk < 16; kk++) {
            int k0 = kk * 8 + tg, k1 = k0 + 4;
            float w0 = (col < 12) ? w_b[k0 * 12 + col] : 0.f;
            float w1 = (col < 12) ? w_b[k1 * 12 + col] : 0.f;
            Bf[kk][0] = to_tf32(w0);
            Bf[kk][1] = to_tf32(w1);
        }
    }
    const int h0 = nh * 8 + 2 * tg;
    const float bb0 = (h0 < 12) ? b_b[h0] : 0.f;
    const float bb1 = (h0 + 1 < 12) ? b_b[h0 + 1] : 0.f;

    for (int idx = t; idx < 768; idx += 256)
        s_w[idx] = __expf(ss[(size_t)i * 768 + idx]) - 0.99f;

    const int col4 = lane * 4;

    for (int chunk = 0; chunk < 12; chunk++) {
        __syncthreads();
        // stage 64 rows of z as tf32 bits (coalesced LDG.128)
        const float* zt = z + ((size_t)(i * 768 + chunk * 64)) * 128;
        #pragma unroll
        for (int k = 0; k < 8; k++) {
            int row = w + k * 8;
            float4 v = __ldg((const float4*)(zt + row * 128 + col4));
            uint4 u;
            u.x = to_tf32(v.x); u.y = to_tf32(v.y);
            u.z = to_tf32(v.z); u.w = to_tf32(v.w);
            *(uint4*)&s_z[row * 132 + col4] = u;
        }
        __syncthreads();

        const uint32_t* sw = s_z + (mt * 16) * 132;
        float c0[4] = {0.f, 0.f, 0.f, 0.f};
        #pragma unroll
        for (int kk = 0; kk < 16; kk++) {
            int co = kk * 8 + tg;
            uint32_t a0 = sw[gp * 132 + co];
            uint32_t a1 = sw[(gp + 8) * 132 + co];
            uint32_t a2 = sw[gp * 132 + co + 4];
            uint32_t a3 = sw[(gp + 8) * 132 + co + 4];
            mma_tf32(c0, a0, a1, a2, a3, Bf[kk][0], Bf[kk][1]);
        }
        // write logits (bias part) into s_l
        const int jb = chunk * 64 + mt * 16;
        if (h0 < 12) {
            s_l[h0 * LP + jb + gp]     = SQ13 * (c0[0] + bb0);
            s_l[h0 * LP + jb + gp + 8] = SQ13 * (c0[2] + bb0);
        }
        if (h0 + 1 < 12) {
            s_l[(h0 + 1) * LP + jb + gp]     = SQ13 * (c0[1] + bb1);
            s_l[(h0 + 1) * LP + jb + gp + 8] = SQ13 * (c0[3] + bb1);
        }
    }
    __syncthreads();

    // add qkp ([i][h][j], coalesced)
    for (int idx = t; idx < 9216; idx += 256) {
        int h = idx / 768, j = idx - h * 768;
        s_l[h * LP + j] += g_qkp[(size_t)i * 9216 + idx];
    }
    __syncthreads();

    // softmax per head (warp per head)
    for (int h = w; h < 12; h += 8) {
        float* lr = &s_l[h * LP];
        float m = -1e30f;
        for (int j = lane; j < 768; j += 32) m = fmaxf(m, lr[j]);
        #pragma unroll
        for (int o = 16; o; o >>= 1) m = fmaxf(m, __shfl_xor_sync(0xffffffffu, m, o));
        float sum = 0.f;
        for (int j = lane; j < 768; j += 32) {
            float p = __expf(lr[j] - m) * s_w[j];
            lr[j] = p;
            sum += p;
        }
        #pragma unroll
        for (int o = 16; o; o >>= 1) sum += __shfl_xor_sync(0xffffffffu, sum, o);
        float inv = 1.f / sum;
        for (int j = lane; j < 768; j += 32) lr[j] *= inv;
    }
    __syncthreads();

    for (int idx = t; idx < 9216; idx += 256) {
        int h = idx / 768, j = idx - h * 768;
        g_a[(size_t)i * 9216 + idx] = s_l[h * LP + j];
    }
    for (int idx = t; idx < 9216; idx += 256) {
        int j = idx / 12, h = idx - j * 12;
        g_aT[(size_t)i * 9216 + idx] = s_l[h * LP + j];
    }
}

// ---------------- opair: o_pair[i][h][c] = sum_j a[i][j][h]*z[i][j][c] ----------------
#define OP_SMEM_FLOATS (8 * 12 * 128)
__global__ __launch_bounds__(256) void opair_kernel(const float* __restrict__ z)
{
    extern __shared__ float s_part[];   // [w][12][128]

    const int i = blockIdx.x;
    const int t = threadIdx.x;
    const int w = t >> 5, lane = t & 31;

    ull acc[6][4];
    #pragma unroll
    for (int q = 0; q < 6; q++)
        #pragma unroll
        for (int c = 0; c < 4; c++) acc[q][c] = 0ull;

    const float* zb = z + (size_t)i * 768 * 128 + lane * 4;
    const float* ab = g_aT + (size_t)i * 9216;

    for (int jb = w * 4; jb < 768; jb += 32) {
        float4 zv[4];
        float4 av[4][3];
        #pragma unroll
        for (int u = 0; u < 4; u++) {
            zv[u] = __ldg((const float4*)(zb + (size_t)(jb + u) * 128));
            av[u][0] = __ldg((const float4*)(ab + (jb + u) * 12));
            av[u][1] = __ldg((const float4*)(ab + (jb + u) * 12 + 4));
            av[u][2] = __ldg((const float4*)(ab + (jb + u) * 12 + 8));
        }
        #pragma unroll
        for (int u = 0; u < 4; u++) {
            ull ap[6];
            ap[0] = pack2(av[u][0].x, av[u][0].y);
            ap[1] = pack2(av[u][0].z, av[u][0].w);
            ap[2] = pack2(av[u][1].x, av[u][1].y);
            ap[3] = pack2(av[u][1].z, av[u][1].w);
            ap[4] = pack2(av[u][2].x, av[u][2].y);
            ap[5] = pack2(av[u][2].z, av[u][2].w);
            float zc[4] = {zv[u].x, zv[u].y, zv[u].z, zv[u].w};
            #pragma unroll
            for (int c = 0; c < 4; c++) {
                ull zz = pack2(zc[c], zc[c]);
                #pragma unroll
                for (int q = 0; q < 6; q++)
                    ffma2(acc[q][c], ap[q], zz);
            }
        }
    }

    #pragma unroll
    for (int q = 0; q < 6; q++) {
        #pragma unroll
        for (int c = 0; c < 4; c++) {
            float2 u = unpack2(acc[q][c]);
            s_part[(w * 12 + 2 * q + 0) * 128 + lane * 4 + c] = u.x;
            s_part[(w * 12 + 2 * q + 1) * 128 + lane * 4 + c] = u.y;
        }
    }
    __syncthreads();

    for (int idx = t; idx < 1536; idx += 256) {
        int h = idx >> 7, c = idx & 127;
        float s = 0.f;
        #pragma unroll
        for (int ww = 0; ww < 8; ww++)
            s += s_part[(ww * 12 + h) * 128 + c];
        g_feats[(size_t)i * FEAT_N + 576 + h * 128 + c] = s;
    }
}

// ---------------- ov: 32-row tiles, 128 threads, grid (24,12); s_a pitch 68 ----------------
__global__ __launch_bounds__(128) void ov_kernel()
{
    __shared__ float s_a[32 * 68];
    __shared__ float s_v[64 * 40];

    const int i0 = blockIdx.x * 32;
    const int h  = blockIdx.y;
    const int t = threadIdx.x;
    const int ig = t >> 3;
    const int og = t & 7;

    float acc[2][5] = {};

    for (int j0 = 0; j0 < 768; j0 += 64) {
        #pragma unroll
        for (int it = 0; it < 4; it++) {
            int idx = t + it * 128;
            int row = idx >> 4, q = idx & 15;
            float4 av = *(const float4*)&g_a[((size_t)(i0 + row) * 12 + h) * 768 + j0 + q * 4];
            *(float4*)&s_a[row * 68 + q * 4] = av;
        }
        #pragma unroll
        for (int it = 0; it < 5; it++) {
            int idx = t + it * 128;
            int jj = idx / 10, q = idx - jj * 10;
            float4 vv = (q < 4)
                ? *(const float4*)&g_v[(j0 + jj) * 192 + h * 16 + q * 4]
                : *(const float4*)&g_vpts[(j0 + jj) * 288 + h * 24 + (q - 4) * 4];
            *(float4*)&s_v[jj * 40 + q * 4] = vv;
        }
        __syncthreads();
        #pragma unroll 8
        for (int jj = 0; jj < 64; jj++) {
            float a0 = s_a[(ig * 2 + 0) * 68 + jj];
            float a1 = s_a[(ig * 2 + 1) * 68 + jj];
            const float* vp = &s_v[jj * 40 + og * 5];
            #pragma unroll
            for (int u = 0; u < 5; u++) {
                float vv = vp[u];
                acc[0][u] += a0 * vv;
                acc[1][u] += a1 * vv;
            }
        }
        __syncthreads();
    }
    #pragma unroll
    for (int r = 0; r < 2; r++) {
        int n = i0 + ig * 2 + r;
        #pragma unroll
        for (int u = 0; u < 5; u++) {
            int e = og * 5 + u;
            if (e < 16) g_feats[(size_t)n * FEAT_N + h * 16 + e] = acc[r][u];
            else        g_optg[n * 288 + h * 24 + (e - 16)] = acc[r][u];
        }
    }
}

// ---------------- optfinal ----------------
__global__ __launch_bounds__(96) void optfinal_kernel(
    const float* __restrict__ rot, const float* __restrict__ trans)
{
    const int n = blockIdx.x;
    const int hp = threadIdx.x;
    float r[9], tr[3];
    #pragma unroll
    for (int e = 0; e < 9; e++) r[e] = rot[n * 9 + e];
    tr[0] = trans[n * 3 + 0]; tr[1] = trans[n * 3 + 1]; tr[2] = trans[n * 3 + 2];

    float gx = g_optg[n * 288 + hp * 3 + 0] - tr[0];
    float gy = g_optg[n * 288 + hp * 3 + 1] - tr[1];
    float gz = g_optg[n * 288 + hp * 3 + 2] - tr[2];
    float l0 = r[0] * gx + r[3] * gy + r[6] * gz;
    float l1 = r[1] * gx + r[4] * gy + r[7] * gz;
    float l2 = r[2] * gx + r[5] * gy + r[8] * gz;

    float* f = &g_feats[(size_t)n * FEAT_N];
    f[192 + hp] = l0;
    f[288 + hp] = l1;
    f[384 + hp] = l2;
    f[480 + hp] = sqrtf(l0 * l0 + l1 * l1 + l2 * l2 + 1e-8f);
}

// ---------------- launch ----------------
extern "C" void kernel_launch(void* const* d_in, const int* in_sizes, int n_in,
                              void* d_out, int out_size)
{
    const float* s       = (const float*)d_in[0];
    const float* z       = (const float*)d_in[1];
    const float* rot     = (const float*)d_in[2];
    const float* trans   = (const float*)d_in[3];
    const float* mask    = (const float*)d_in[4];
    const float* ss      = (const float*)d_in[5];
    const float* w_q     = (const float*)d_in[6];
    const float* b_q     = (const float*)d_in[7];
    const float* w_kv    = (const float*)d_in[8];
    const float* b_kv    = (const float*)d_in[9];
    const float* w_qp    = (const float*)d_in[10];
    const float* b_qp    = (const float*)d_in[11];
    const float* w_kvp   = (const float*)d_in[12];
    const float* b_kvp   = (const float*)d_in[13];
    const float* w_b     = (const float*)d_in[14];
    const float* b_b     = (const float*)d_in[15];
    const float* head_w  = (const float*)d_in[16];
    const float* w_out   = (const float*)d_in[17];
    const float* b_out   = (const float*)d_in[18];
    float* out = (float*)d_out;

    float* proj;  cudaGetSymbolAddress((void**)&proj, g_proj);
    float* feats; cudaGetSymbolAddress((void**)&feats, g_feats);

    static bool attr_done = false;
    if (!attr_done) {
        cudaFuncSetAttribute(opair_kernel,
                             cudaFuncAttributeMaxDynamicSharedMemorySize,
                             OP_SMEM_FLOATS * 4);
        cudaFuncSetAttribute(attnsm_kernel,
                             cudaFuncAttributeMaxDynamicSharedMemorySize,
                             AS_SMEM_BYTES);
        attr_done = true;
    }

    // K1: projections (768 x 1152)
    gemm_kernel<<<dim3(18, 24), 256>>>(
        s, CS, w_q, w_kv, w_qp, w_kvp, b_q, b_kv, b_qp, b_kvp,
        192, 576, 720, 1152, proj, PROJ_N);

    // K2: split k/v, rotate points, build logit-GEMM rows
    prep_kernel<<<NN, 384>>>(rot, trans, head_w);

    // K2b: qk+pts+mask logits as 30-dim GEMM
    qkpts_kernel<<<dim3(12, 12, 12), 256>>>(mask);

    // K3: fused z-bias MMA + qkp + softmax (z pass 1)
    attnsm_kernel<<<NN, 256, AS_SMEM_BYTES>>>(z, ss, w_b, b_b);

    // K3b: o_pair (z pass 2)
    opair_kernel<<<NN, 256, OP_SMEM_FLOATS * 4>>>(z);

    // K4: o and o_pt accumulation
    ov_kernel<<<dim3(24, 12), 128>>>();

    // K5: finalize o_pt + norms
    optfinal_kernel<<<NN, 96>>>(rot, trans);

    // K6: output GEMM (768 x 384, K=2112)
    gemm_kernel<<<dim3(6, 24), 256>>>(
        feats, FEAT_N, w_out, w_out, w_out, w_out, b_out, b_out, b_out, b_out,
        384, 384, 384, 384, out, CS);
}